// round 11
// baseline (speedup 1.0000x reference)
#include <cuda_runtime.h>
#include <cstdint>

#define T_STEPS 1000
#define BATCH   2048
#define FEAT    40
#define H1      8
#define H2      6
#define G1      32

#define CT      8
#define NCHUNK  (T_STEPS / CT)      // 125
#define SITES   (CT * FEAT / 4)     // 80 float4 per chunk

typedef unsigned long long u64;

// ---------------- helpers ----------------
__device__ __forceinline__ u64 pack2(float x, float y) {
    u64 r; asm("mov.b64 %0, {%1, %2};" : "=l"(r) : "f"(x), "f"(y)); return r;
}
__device__ __forceinline__ void unpack2(u64 v, float& x, float& y) {
    asm("mov.b64 {%0, %1}, %2;" : "=f"(x), "=f"(y) : "l"(v));
}
__device__ __forceinline__ u64 fma2(u64 a, u64 b, u64 c) {
    u64 d; asm("fma.rn.f32x2 %0, %1, %2, %3;" : "=l"(d) : "l"(a), "l"(b), "l"(c)); return d;
}
__device__ __forceinline__ u64 mul2(u64 a, u64 b) {
    u64 d; asm("mul.rn.f32x2 %0, %1, %2;" : "=l"(d) : "l"(a), "l"(b)); return d;
}
__device__ __forceinline__ u64 add2(u64 a, u64 b) {
    u64 d; asm("add.rn.f32x2 %0, %1, %2;" : "=l"(d) : "l"(a), "l"(b)); return d;
}
__device__ __forceinline__ u64 scale2(u64 v, float s) {
    float a, b; unpack2(v, a, b); return pack2(a * s, b * s);
}
__device__ __forceinline__ float hadd2(u64 v) {
    float a, b; unpack2(v, a, b); return a + b;
}
__device__ __forceinline__ float tanha(float x) {
    float r; asm("tanh.approx.f32 %0, %1;" : "=f"(r) : "f"(x)); return r;
}
__device__ __forceinline__ float shflf(float v, int src) {
    return __shfl_sync(0xffffffffu, v, src & 31);
}
__device__ __forceinline__ float shflx(float v, int m) {
    return __shfl_xor_sync(0xffffffffu, v, m);
}
__device__ __forceinline__ uint32_t smem_u32(const void* p) {
    uint32_t a;
    asm("{ .reg .u64 t; cvta.to.shared.u64 t, %1; cvt.u32.u64 %0, t; }" : "=r"(a) : "l"(p));
    return a;
}
__device__ __forceinline__ void cp_async16(uint32_t saddr, const void* gaddr) {
    asm volatile("cp.async.cg.shared.global [%0], [%1], 16;" :: "r"(saddr), "l"(gaddr));
}
__device__ __forceinline__ void cp_commit() {
    asm volatile("cp.async.commit_group;" ::: "memory");
}
template <int N>
__device__ __forceinline__ void cp_wait() {
    asm volatile("cp.async.wait_group %0;" :: "n"(N) : "memory");
}
#define BAR64() asm volatile("bar.sync 0, 64;" ::: "memory")

// ============================================================================
// consumer step: layer1(i) + layer2(i-1); XOR-shuffle gathering (R10 proven).
// slab shs[2][24], INTERLEAVED: [2j]=h1[j], [2j+1]=x2[j] (j<8); [16..21]=h2.
// Merged MAC: w12p[j]=(w1[j], wi2[j]) against pairs (h1[j], x2[j]):
//   .x accumulates layer1 hidden MAC, .y accumulates layer2 x2 MAC.
// L1 gates at lanes: i 0-7 | f 8-15 | g 16-23 | o 24-31  (c1 on lanes 8-15)
// L2 gates at lanes: i 0-5 | f 8-13 | g 16-21 | o 24-29  (c2 on lanes 8-13)
// ============================================================================
template <int RD>
__device__ __forceinline__ void rec_step(
    float en, int lane, float gval,
    float (*shs)[24],
    const u64* __restrict__ w12p, const u64* __restrict__ wh2p, u64 bias02,
    float cn1, float ca1, float cn2, float ca2,
    float& c1, float& c2)
{
    constexpr int WR = RD ^ 1;

    const ulonglong2* hp = reinterpret_cast<const ulonglong2*>(&shs[RD][0]);
    ulonglong2 p0 = hp[0], p1 = hp[1], p2 = hp[2], p3 = hp[3];   // (h1[j],x2[j]) pairs
    ulonglong2 hq = hp[4];                                        // h2[0..3]
    u64        ht = reinterpret_cast<const u64*>(&shs[RD][0])[10]; // h2[4..5]

    // merged dual-layer MAC
    u64 A = fma2(p0.x, w12p[0], bias02);
    u64 B = mul2(p0.y, w12p[1]);
    A = fma2(p1.x, w12p[2], A);
    B = fma2(p1.y, w12p[3], B);
    A = fma2(p2.x, w12p[4], A);
    B = fma2(p2.y, w12p[5], B);
    A = fma2(p3.x, w12p[6], A);
    B = fma2(p3.y, w12p[7], B);
    u64 H = mul2(hq.x, wh2p[0]);
    u64 K = mul2(hq.y, wh2p[1]);
    H = fma2(ht, wh2p[2], H);
    u64 AB = add2(A, B);
    float gx, gy; unpack2(AB, gx, gy);
    float g1 = gval + gx;
    float g2 = gy + hadd2(add2(H, K));

    float a1 = fmaf(cn1, tanha(g1), ca1);
    float a2 = fmaf(cn2, tanha(g2), ca2);

    // XOR gathers
    float s1 = shflx(a1, 16);
    float s2 = shflx(a2, 16);
    float q1 = a1 * s1;
    float q2 = a2 * s2;
    float t1 = shflx(q1, 8);     // lanes 8-15 <- i*g (L1)
    float t2 = shflx(q2, 8);     // lanes 8-13 <- i*g (L2)

    // state owners: lanes 8-15 hold a1=f, s1=o
    c1 = fmaf(a1, c1, t1);
    float h1v = s1 * tanha(c1);
    float x2v = tanha(h1v);

    // lanes 8-13 hold a2=f2, s2=o2
    c2 = en * fmaf(a2, c2, t2);
    float h2v = s2 * tanha(c2);

    if (lane >= 8 && lane < 16)
        *reinterpret_cast<u64*>(&shs[WR][2 * (lane - 8)]) = pack2(h1v, x2v);  // STS.64
    if (lane >= 8 && lane < 14)
        shs[WR][8 + lane] = h2v;                                              // STS.32
    __syncwarp();
}

// ============================================================================
// producer gate compute: rows 4h..4h+3, gates (l, l+16); quad STS.128 stores.
// ============================================================================
__device__ __forceinline__ void produce_gates(
    const float (*src)[FEAT], float4* __restrict__ dstq,   // dstq = &sgate[buf][h][0]
    int l, int h,
    const u64* __restrict__ wA, const u64* __restrict__ wB,
    float bA, float bB)
{
    u64 a0[4], a1[4], b0[4], b1[4];
#pragma unroll
    for (int r = 0; r < 4; r++) {
        a0[r] = pack2(bA, 0.f); a1[r] = 0ull;
        b0[r] = pack2(bB, 0.f); b1[r] = 0ull;
    }
#pragma unroll
    for (int q = 0; q < FEAT / 4; q++) {
        u64 wa0 = wA[2 * q], wa1 = wA[2 * q + 1];
        u64 wb0 = wB[2 * q], wb1 = wB[2 * q + 1];
#pragma unroll
        for (int r = 0; r < 4; r++) {
            ulonglong2 v = *reinterpret_cast<const ulonglong2*>(&src[4 * h + r][4 * q]);
            a0[r] = fma2(wa0, v.x, a0[r]);
            a1[r] = fma2(wa1, v.y, a1[r]);
            b0[r] = fma2(wb0, v.x, b0[r]);
            b1[r] = fma2(wb1, v.y, b1[r]);
        }
    }
    float4 fA, fB;
    fA.x = hadd2(add2(a0[0], a1[0])); fA.y = hadd2(add2(a0[1], a1[1]));
    fA.z = hadd2(add2(a0[2], a1[2])); fA.w = hadd2(add2(a0[3], a1[3]));
    fB.x = hadd2(add2(b0[0], b1[0])); fB.y = hadd2(add2(b0[1], b1[1]));
    fB.z = hadd2(add2(b0[2], b1[2])); fB.w = hadd2(add2(b0[3], b1[3]));
    dstq[l]      = fA;    // STS.128
    dstq[l + 16] = fB;    // STS.128
}

// ============================================================================
// fused producer/consumer kernel: 1 block = 1 batch element, 2 warps.
// ============================================================================
__global__ void __launch_bounds__(64)
fused_pc(const float* __restrict__ x,
         const float* __restrict__ W_ih1,
         const float* __restrict__ W_hh1,
         const float* __restrict__ b_ih1,
         const float* __restrict__ b_hh1,
         const float* __restrict__ W_ih2,
         const float* __restrict__ W_hh2,
         const float* __restrict__ b_ih2,
         const float* __restrict__ b_hh2,
         const float* __restrict__ W_fc,
         const float* __restrict__ b_fc,
         float* __restrict__ out) {
    __shared__ __align__(16) float4 sgate[2][2][G1];   // [buf][t-quad][gate] = 4 steps
    __shared__ __align__(16) float  sx[2][CT][FEAT];   // x staging (cp.async)
    __shared__ __align__(16) float  shs[2][24];        // interleaved h1/x2 + h2

    int tid  = threadIdx.x;
    int lane = tid & 31;
    int wid  = tid >> 5;
    int b    = blockIdx.x;

    if (wid == 1) {
        // ======================= PRODUCER =======================
        int l = lane & 15, h = lane >> 4;     // h = row block (rows 4h..4h+3)
        int gA = l, gB = l + 16;
        float cmA = 0.5f;                     // gates 0..15: sigmoid
        float cmB = (l < 8) ? 1.0f : 0.5f;    // 16..23 tanh, 24..31 sigmoid

        u64 wA[FEAT / 2], wB[FEAT / 2];
        {
            const u64* wra = reinterpret_cast<const u64*>(W_ih1 + gA * FEAT);
            const u64* wrb = reinterpret_cast<const u64*>(W_ih1 + gB * FEAT);
#pragma unroll
            for (int p = 0; p < FEAT / 2; p++) {
                wA[p] = scale2(wra[p], cmA);
                wB[p] = scale2(wrb[p], cmB);
            }
        }
        float bA = cmA * (b_ih1[gA] + b_hh1[gA]);
        float bB = cmB * (b_ih1[gB] + b_hh1[gB]);

        const float4* xb = reinterpret_cast<const float4*>(x + (size_t)b * T_STEPS * FEAT);
        uint32_t sx0 = smem_u32(&sx[0][0][0]);
        uint32_t sx1 = smem_u32(&sx[1][0][0]);

        // issue chunks 0,1
#pragma unroll
        for (int i = 0; i < 3; i++) {
            int s = lane + 32 * i;
            if (s < SITES) cp_async16(sx0 + 16 * s, xb + s);
        }
        cp_commit();
#pragma unroll
        for (int i = 0; i < 3; i++) {
            int s = lane + 32 * i;
            if (s < SITES) cp_async16(sx1 + 16 * s, xb + SITES + s);
        }
        cp_commit();
        cp_wait<1>();
        __syncwarp();

        produce_gates(sx[0], &sgate[0][h][0], l, h, wA, wB, bA, bB);
        BAR64();

#pragma unroll 1
        for (int c = 0; c < NCHUNK; c++) {
            if (c + 1 < NCHUNK) {
                int c2i = (c + 2 < NCHUNK) ? c + 2 : NCHUNK - 1;
                uint32_t dst = (c & 1) ? sx1 : sx0;
#pragma unroll
                for (int i = 0; i < 3; i++) {
                    int s = lane + 32 * i;
                    if (s < SITES) cp_async16(dst + 16 * s, xb + (size_t)c2i * SITES + s);
                }
                cp_commit();
                cp_wait<1>();      // chunk c+1 resident
                __syncwarp();

                produce_gates(sx[(c + 1) & 1], &sgate[(c + 1) & 1][h][0],
                              l, h, wA, wB, bA, bB);
            }
            BAR64();
        }
        cp_wait<0>();
    } else {
        // ======================= CONSUMER =======================
        // layer1 activation constants by quarter (g-quarter = lanes 16-23: tanh)
        bool t1c = ((lane >> 3) == 2);
        float cm1 = t1c ? 1.f : 0.5f, cn1 = t1c ? 1.f : 0.5f, ca1 = t1c ? 0.f : 0.5f;
        // layer2 quarter-aligned: valid = (lane&7)<6 && lane<30
        bool v2 = ((lane & 7) < 6) && (lane < 30);
        int g2i = lane - 2 * (lane >> 3);
        bool t2c = (lane >= 16 && lane < 22);
        float cm2 = t2c ? 1.f : 0.5f, cn2 = t2c ? 1.f : 0.5f, ca2 = t2c ? 0.f : 0.5f;

        // merged weight pairs: (w1[j], wi2[j])
        u64 w12p[H1];
#pragma unroll
        for (int j = 0; j < H1; j++) {
            float wa = cm1 * W_hh1[lane * H1 + j];
            float wb = v2 ? (cm2 * W_ih2[g2i * H1 + j]) : 0.f;
            w12p[j] = pack2(wa, wb);
        }
        u64 wh2p[H2 / 2];
#pragma unroll
        for (int j = 0; j < H2 / 2; j++) wh2p[j] = 0ull;
        float b2s = 0.f;
        if (v2) {
#pragma unroll
            for (int j = 0; j < H2 / 2; j++)
                wh2p[j] = pack2(cm2 * W_hh2[g2i * H2 + 2 * j], cm2 * W_hh2[g2i * H2 + 2 * j + 1]);
            b2s = cm2 * (b_ih2[g2i] + b_hh2[g2i]);
        }
        u64 bias02 = pack2(0.f, b2s);

        if (lane < 24) shs[1][lane] = 0.f;
        float c1 = 0.f, c2 = 0.f;
        BAR64();

#pragma unroll 1
        for (int c = 0; c < NCHUNK; c++) {
            float en0 = (c == 0) ? 0.f : 1.f;
            float4 q0 = sgate[c & 1][0][lane];   // t 0..3 for this gate
            rec_step<1>(en0, lane, q0.x, shs, w12p, wh2p, bias02,
                        cn1, ca1, cn2, ca2, c1, c2);
            rec_step<0>(1.f, lane, q0.y, shs, w12p, wh2p, bias02,
                        cn1, ca1, cn2, ca2, c1, c2);
            rec_step<1>(1.f, lane, q0.z, shs, w12p, wh2p, bias02,
                        cn1, ca1, cn2, ca2, c1, c2);
            rec_step<0>(1.f, lane, q0.w, shs, w12p, wh2p, bias02,
                        cn1, ca1, cn2, ca2, c1, c2);
            float4 q1 = sgate[c & 1][1][lane];   // t 4..7
            rec_step<1>(1.f, lane, q1.x, shs, w12p, wh2p, bias02,
                        cn1, ca1, cn2, ca2, c1, c2);
            rec_step<0>(1.f, lane, q1.y, shs, w12p, wh2p, bias02,
                        cn1, ca1, cn2, ca2, c1, c2);
            rec_step<1>(1.f, lane, q1.z, shs, w12p, wh2p, bias02,
                        cn1, ca1, cn2, ca2, c1, c2);
            rec_step<0>(1.f, lane, q1.w, shs, w12p, wh2p, bias02,
                        cn1, ca1, cn2, ca2, c1, c2);
            BAR64();
        }

        // ---- epilogue: layer2(999) from shs[1] (x2(999), h2(998)) ----
        {
            const ulonglong2* hp = reinterpret_cast<const ulonglong2*>(&shs[1][0]);
            ulonglong2 p0 = hp[0], p1 = hp[1], p2 = hp[2], p3 = hp[3];
            ulonglong2 hq = hp[4];
            u64        ht = reinterpret_cast<const u64*>(&shs[1][0])[10];

            u64 A = fma2(p0.x, w12p[0], bias02);
            u64 B = mul2(p0.y, w12p[1]);
            A = fma2(p1.x, w12p[2], A);
            B = fma2(p1.y, w12p[3], B);
            A = fma2(p2.x, w12p[4], A);
            B = fma2(p2.y, w12p[5], B);
            A = fma2(p3.x, w12p[6], A);
            B = fma2(p3.y, w12p[7], B);
            u64 H = mul2(hq.x, wh2p[0]);
            u64 K = mul2(hq.y, wh2p[1]);
            H = fma2(ht, wh2p[2], H);
            float gx, gy; unpack2(add2(A, B), gx, gy);
            float g2 = gy + hadd2(add2(H, K));

            float a2 = fmaf(cn2, tanha(g2), ca2);
            float s2 = shflx(a2, 16);
            float q2 = a2 * s2;
            float t2 = shflx(q2, 8);
            c2 = fmaf(a2, c2, t2);                 // lanes 8-13
            float tx = tanha(s2 * tanha(c2));      // tanh(h2(999)) at lanes 8-13

            float s = b_fc[0];
#pragma unroll
            for (int j = 0; j < H2; j++)
                s = fmaf(shflf(tx, 8 + j), W_fc[j], s);
            if (lane == 0)
                out[b] = fmaf(0.5f, tanha(0.5f * s), 0.5f);
        }
    }
}

// ============================================================================
extern "C" void kernel_launch(void* const* d_in, const int* in_sizes, int n_in,
                              void* d_out, int out_size) {
    const float* x     = (const float*)d_in[0];
    const float* W_ih1 = (const float*)d_in[1];
    const float* W_hh1 = (const float*)d_in[2];
    const float* b_ih1 = (const float*)d_in[3];
    const float* b_hh1 = (const float*)d_in[4];
    const float* W_ih2 = (const float*)d_in[5];
    const float* W_hh2 = (const float*)d_in[6];
    const float* b_ih2 = (const float*)d_in[7];
    const float* b_hh2 = (const float*)d_in[8];
    const float* W_fc  = (const float*)d_in[9];
    const float* b_fc  = (const float*)d_in[10];
    float* out = (float*)d_out;

    fused_pc<<<BATCH, 64>>>(x, W_ih1, W_hh1, b_ih1, b_hh1,
                            W_ih2, W_hh2, b_ih2, b_hh2, W_fc, b_fc, out);
}